// round 10
// baseline (speedup 1.0000x reference)
#include <cuda_runtime.h>
#include <cstdint>

#define B_  4
#define L_  2048
#define H_  256
#define NH_ 8
#define DH_ 32
#define M_  (B_*L_)   // 8192 rows

// ---------------------------------------------------------------------------
// Global scratch (allocation-free rule: __device__ globals)
// K(eff) split bf16 words, layout [b][h][tile32][key64][20 words] (16 used)
// V^T   split bf16 words, layout [b][h][tile32][drow32][36 words] (32 used)
// ---------------------------------------------------------------------------
__device__ __align__(16) uint32_t g_kh[B_*NH_*32*64*20];
__device__ __align__(16) uint32_t g_kl[B_*NH_*32*64*20];
__device__ __align__(16) uint32_t g_vh[B_*NH_*32*32*36];
__device__ __align__(16) uint32_t g_vl[B_*NH_*32*32*36];
__device__ __align__(16) float    g_hidden[M_ * H_];
__device__ int g_mflag[B_];   // 1 = no masked keys in this batch row

// ---------------------------------------------------------------------------
// helpers
// ---------------------------------------------------------------------------
__device__ __forceinline__ float ex2f(float x) {
    float r; asm("ex2.approx.f32 %0, %1;" : "=f"(r) : "f"(x)); return r;
}
__device__ __forceinline__ void mma16(float c[4], const uint32_t a[4],
                                      uint32_t b0, uint32_t b1) {
    asm("mma.sync.aligned.m16n8k16.row.col.f32.bf16.bf16.f32 "
        "{%0,%1,%2,%3},{%4,%5,%6,%7},{%8,%9},{%0,%1,%2,%3};"
        : "+f"(c[0]), "+f"(c[1]), "+f"(c[2]), "+f"(c[3])
        : "r"(a[0]), "r"(a[1]), "r"(a[2]), "r"(a[3]), "r"(b0), "r"(b1));
}
// pack (lo=x, hi=y) into bf16x2; split2 also returns residual word
__device__ __forceinline__ uint32_t packbf(float x, float y) {
    uint32_t r; asm("cvt.rn.bf16x2.f32 %0, %1, %2;" : "=r"(r) : "f"(y), "f"(x));
    return r;
}
__device__ __forceinline__ void split2(float x, float y,
                                       uint32_t& hw, uint32_t& lw) {
    hw = packbf(x, y);
    float xh = __uint_as_float(hw << 16);
    float yh = __uint_as_float(hw & 0xffff0000u);
    lw = packbf(x - xh, y - yh);
}
__device__ __forceinline__ void cp16(uint32_t saddr, const void* gaddr) {
    asm volatile("cp.async.cg.shared.global [%0], [%1], 16;"
                 :: "r"(saddr), "l"(gaddr));
}
__device__ __forceinline__ void cp_commit() {
    asm volatile("cp.async.commit_group;");
}
__device__ __forceinline__ void cp_wait0() {
    asm volatile("cp.async.wait_group 0;" ::: "memory");
}

// word-position permutations: u = w&7, s = w>>3
// K rows have 16 words: pos = (u&3)*4 + 2s + (u>>2)
// V rows have 32 words: pos = (u&3)*8 + 2s + (u>>2)
__device__ __forceinline__ int kpos(int w) {
    return ((w & 3) << 2) + ((w >> 3) << 1) + ((w >> 2) & 1);
}
__device__ __forceinline__ int vpos(int w) {
    return ((w & 3) << 3) + ((w >> 3) << 1) + ((w >> 2) & 1);
}

// ---------------------------------------------------------------------------
// mask flag: g_mflag[b] = 1 iff mask[b][*] all nonzero
// ---------------------------------------------------------------------------
__global__ __launch_bounds__(128)
void maskflag(const int* __restrict__ mask)
{
    __shared__ int s[128];
    const int b = blockIdx.x, tid = threadIdx.x;
    int all1 = 1;
    for (int i = tid; i < L_; i += 128) all1 &= (mask[b * L_ + i] != 0);
    s[tid] = all1;
    __syncthreads();
    for (int st = 64; st; st >>= 1) {
        if (tid < st) s[tid] &= s[tid + st];
        __syncthreads();
    }
    if (tid == 0) g_mflag[b] = s[0];
}

// ---------------------------------------------------------------------------
// V prep: v [b][kv][h*32+d] f32  ->  g_vh/g_vl transposed split words
// ---------------------------------------------------------------------------
__global__ __launch_bounds__(128)
void vprep(const float* __restrict__ v)
{
    __shared__ float sv[64 * 36];
    __shared__ uint32_t swh[32 * 36], swl[32 * 36];
    const int bx = blockIdx.x;
    const int kt = bx & 31, h = (bx >> 5) & 7, b = bx >> 8;
    const int tid = threadIdx.x;
    const float* src = v + ((size_t)(b * L_ + kt * 64)) * H_ + h * 32;

    #pragma unroll
    for (int u = 0; u < 4; u++) {
        int idx = tid + u * 128;
        int row = idx >> 3, c4 = idx & 7;
        *(float4*)&sv[row * 36 + c4 * 4] = *(const float4*)&src[row * H_ + c4 * 4];
    }
    __syncthreads();
    #pragma unroll
    for (int u = 0; u < 8; u++) {
        int idx = tid + u * 128;
        int drow = idx >> 5, w = idx & 31;
        float x = sv[(2 * w) * 36 + drow];
        float y = sv[(2 * w + 1) * 36 + drow];
        uint32_t hw, lw; split2(x, y, hw, lw);
        int p = vpos(w);
        swh[drow * 36 + p] = hw;
        swl[drow * 36 + p] = lw;
    }
    __syncthreads();
    uint32_t* gh = g_vh + (size_t)bx * 1152;
    uint32_t* gl = g_vl + (size_t)bx * 1152;
    #pragma unroll
    for (int u = 0; u < 9; u++) {
        int idx = tid + u * 128;
        if (idx < 1152) { gh[idx] = swh[idx]; gl[idx] = swl[idx]; }
    }
}

// ---------------------------------------------------------------------------
// GEMM (bf16 3x, m16n8k16): out[m,n] = A·W^T + bias (+add). BM=128,BN=64,BK=32.
// smem holds packed bf16x2 hi/lo words, 20-word row stride (16 used).
// Register prefetch of next k-tile overlaps LDG with mma.
// ---------------------------------------------------------------------------
#define GAH 0
#define GAL (128 * 20)
#define GWH (2 * 128 * 20)
#define GWL (2 * 128 * 20 + 64 * 20)
#define GEMM_SMEM_WORDS (2 * 128 * 20 + 2 * 64 * 20)
#define GEMM_SMEM_BYTES (GEMM_SMEM_WORDS * 4)

template<bool KEFF>
__global__ __launch_bounds__(256)
void gemm_tc(const float* __restrict__ Ain,
             const float* __restrict__ W,
             const float* __restrict__ bias,
             const float* __restrict__ add,
             float* __restrict__ outp)
{
    extern __shared__ uint32_t smw[];
    const float* A = KEFF ? Ain : g_hidden;

    const int m0  = blockIdx.y * 128;
    const int n0  = blockIdx.x * 64;
    const int tid = threadIdx.x;
    const int warp   = tid >> 5;
    const int lane   = tid & 31;
    const int warp_m = warp >> 1;
    const int warp_n = warp & 1;
    const int g = lane >> 2;
    const int t = lane & 3;

    float acc[2][4][4] = {};

    float4 xa[4], xw[2];
    #pragma unroll
    for (int u = 0; u < 4; u++) {
        int idx = tid + u * 256;
        xa[u] = *(const float4*)&A[(size_t)(m0 + (idx >> 3)) * H_ + (idx & 7) * 4];
    }
    #pragma unroll
    for (int u = 0; u < 2; u++) {
        int idx = tid + u * 256;
        xw[u] = *(const float4*)&W[(size_t)(n0 + (idx >> 3)) * H_ + (idx & 7) * 4];
    }

    for (int k0 = 0; k0 < H_; k0 += 32) {
        #pragma unroll
        for (int u = 0; u < 4; u++) {
            int idx = tid + u * 256;
            int row = idx >> 3, c4 = idx & 7;
            uint32_t h0, l0, h1, l1;
            split2(xa[u].x, xa[u].y, h0, l0);
            split2(xa[u].z, xa[u].w, h1, l1);
            *(uint2*)&smw[GAH + row * 20 + c4 * 2] = make_uint2(h0, h1);
            *(uint2*)&smw[GAL + row * 20 + c4 * 2] = make_uint2(l0, l1);
        }
        #pragma unroll
        for (int u = 0; u < 2; u++) {
            int idx = tid + u * 256;
            int row = idx >> 3, c4 = idx & 7;
            uint32_t h0, l0, h1, l1;
            split2(xw[u].x, xw[u].y, h0, l0);
            split2(xw[u].z, xw[u].w, h1, l1);
            *(uint2*)&smw[GWH + row * 20 + c4 * 2] = make_uint2(h0, h1);
            *(uint2*)&smw[GWL + row * 20 + c4 * 2] = make_uint2(l0, l1);
        }
        __syncthreads();

        if (k0 + 32 < H_) {
            #pragma unroll
            for (int u = 0; u < 4; u++) {
                int idx = tid + u * 256;
                xa[u] = *(const float4*)&A[(size_t)(m0 + (idx >> 3)) * H_ +
                                           k0 + 32 + (idx & 7) * 4];
            }
            #pragma unroll
            for (int u = 0; u < 2; u++) {
                int idx = tid + u * 256;
                xw[u] = *(const float4*)&W[(size_t)(n0 + (idx >> 3)) * H_ +
                                           k0 + 32 + (idx & 7) * 4];
            }
        }

        #pragma unroll
        for (int s = 0; s < 2; s++) {
            uint32_t ah[2][4], al[2][4];
            #pragma unroll
            for (int mt = 0; mt < 2; mt++) {
                int r0 = (warp_m * 32 + mt * 16 + g) * 20 + 8 * s + t;
                ah[mt][0] = smw[GAH + r0];
                ah[mt][1] = smw[GAH + r0 + 160];      // +8 rows
                ah[mt][2] = smw[GAH + r0 + 4];
                ah[mt][3] = smw[GAH + r0 + 164];
                al[mt][0] = smw[GAL + r0];
                al[mt][1] = smw[GAL + r0 + 160];
                al[mt][2] = smw[GAL + r0 + 4];
                al[mt][3] = smw[GAL + r0 + 164];
            }
            #pragma unroll
            for (int nt = 0; nt < 4; nt++) {
                int rw = (warp_n * 32 + nt * 8 + g) * 20 + 8 * s + t;
                uint32_t wh0 = smw[GWH + rw];
                uint32_t wh1 = smw[GWH + rw + 4];
                uint32_t wl0 = smw[GWL + rw];
                uint32_t wl1 = smw[GWL + rw + 4];
                #pragma unroll
                for (int mt = 0; mt < 2; mt++) {
                    mma16(acc[mt][nt], al[mt], wh0, wh1);
                    mma16(acc[mt][nt], ah[mt], wl0, wl1);
                    mma16(acc[mt][nt], ah[mt], wh0, wh1);
                }
            }
        }
        __syncthreads();
    }

    #pragma unroll
    for (int mt = 0; mt < 2; mt++) {
        #pragma unroll
        for (int nt = 0; nt < 4; nt++) {
            int n  = n0 + warp_n * 32 + nt * 8 + 2 * t;
            int mA = m0 + warp_m * 32 + mt * 16 + g;
            int mB = mA + 8;
            float2 bs = *(const float2*)&bias[n];
            float x0 = acc[mt][nt][0] + bs.x, x1 = acc[mt][nt][1] + bs.y;
            float y0 = acc[mt][nt][2] + bs.x, y1 = acc[mt][nt][3] + bs.y;
            if (KEFF) {
                float2 a0 = *(const float2*)&add[(size_t)mA * H_ + n];
                float2 a1 = *(const float2*)&add[(size_t)mB * H_ + n];
                x0 += a0.x; x1 += a0.y; y0 += a1.x; y1 += a1.y;
                int h = n >> 5;
                int wd = (n & 31) >> 1;
                int p = kpos(wd);
                uint32_t hw, lw;
                {
                    int bi = mA >> 11, l = mA & 2047;
                    size_t base = (((size_t)(bi * NH_ + h) * 32 + (l >> 6)) * 64
                                   + (l & 63)) * 20 + p;
                    split2(x0, x1, hw, lw);
                    g_kh[base] = hw; g_kl[base] = lw;
                }
                {
                    int bi = mB >> 11, l = mB & 2047;
                    size_t base = (((size_t)(bi * NH_ + h) * 32 + (l >> 6)) * 64
                                   + (l & 63)) * 20 + p;
                    split2(y0, y1, hw, lw);
                    g_kh[base] = hw; g_kl[base] = lw;
                }
            } else {
                *(float2*)&outp[(size_t)mA * H_ + n] = make_float2(x0, x1);
                *(float2*)&outp[(size_t)mB * H_ + n] = make_float2(y0, y1);
            }
        }
    }
}

// ---------------------------------------------------------------------------
// Flash attention, bf16x3 via m16n8k16, static softmax in exp2 domain.
// P lives in registers (S C-fragment == PV A-fragment). Per-HALF pipeline:
// S-mma -> exp2/pack -> PV-mma, so AP/c registers are short-lived and
// tensor/MUFU/LDS mix in the issue stream. 3 CTAs/SM via launch bounds.
// BQ=128 (8 warps, 256 threads), BK=64, cp.async double-buffered K/V.
// ---------------------------------------------------------------------------
#define OKH 0
#define OKL 1280
#define OVH 2560
#define OVL 3712
#define OMS 4864
#define BUFSZ 4928
#define ATTN_SMEM_WORDS (2 * BUFSZ)
#define ATTN_SMEM_BYTES (ATTN_SMEM_WORDS * 4)

__device__ __forceinline__ void fill_tile(uint32_t sbase, int bufbase,
                                          int bh, int kt,
                                          const int* __restrict__ maskb)
{
    const int tid = threadIdx.x;
    size_t kb = ((size_t)bh * 32 + kt) * 1280;
    size_t vb = ((size_t)bh * 32 + kt) * 1152;
    const uint32_t* gkh = g_kh + kb;
    const uint32_t* gkl = g_kl + kb;
    const uint32_t* gvh = g_vh + vb;
    const uint32_t* gvl = g_vl + vb;
    #pragma unroll
    for (int u = 0; u < 2; u++) {
        int i = tid + u * 256;
        if (i < 320) {
            cp16(sbase + (bufbase + OKH + i * 4) * 4, gkh + i * 4);
            cp16(sbase + (bufbase + OKL + i * 4) * 4, gkl + i * 4);
        }
    }
    #pragma unroll
    for (int u = 0; u < 2; u++) {
        int i = tid + u * 256;
        if (i < 288) {
            cp16(sbase + (bufbase + OVH + i * 4) * 4, gvh + i * 4);
            cp16(sbase + (bufbase + OVL + i * 4) * 4, gvl + i * 4);
        }
    }
    if (tid < 16)
        cp16(sbase + (bufbase + OMS + tid * 4) * 4, maskb + kt * 64 + tid * 4);
    cp_commit();
}

__global__ __launch_bounds__(256, 3)
void attn_tc(const float* __restrict__ q,
             const int*   __restrict__ mask,
             const float* __restrict__ scale_w)
{
    extern __shared__ uint32_t smu[];
    const uint32_t sbase = (uint32_t)__cvta_generic_to_shared(smu);

    const int b   = blockIdx.z;
    const int h   = blockIdx.y;
    const int q0  = blockIdx.x * 128;
    const int bh  = b * NH_ + h;
    const int tid = threadIdx.x;
    const int warp = tid >> 5;
    const int lane = tid & 31;
    const int g = lane >> 2;
    const int t = lane & 3;
    // exp2-domain: fold log2e into the Q pre-scale; p = exp2(s' - EOFF2)
    const float rs = 0.17677669529663687f * 1.4426950408889634f;
    const float EOFF2 = 23.083120654223414f;   // 16 * log2e

    const int r0l = warp * 16 + g;
    const int r1l = r0l + 8;
    const int* maskb = mask + b * L_;
    const int noMask = g_mflag[b];

    // ---- Q fragments: 2 k16-steps, split bf16 ----
    const float s0 = scale_w[h * L_ + q0 + r0l] * rs;
    const float s1 = scale_w[h * L_ + q0 + r1l] * rs;
    const float* qb = q + (size_t)(b * L_ + q0) * H_ + h * DH_;

    uint32_t qh[2][4], ql[2][4];
    #pragma unroll
    for (int s = 0; s < 2; s++) {
        float2 v0 = *(const float2*)&qb[r0l * H_ + s * 16 + 2 * t];
        float2 v2 = *(const float2*)&qb[r0l * H_ + s * 16 + 2 * t + 8];
        float2 v1 = *(const float2*)&qb[r1l * H_ + s * 16 + 2 * t];
        float2 v3 = *(const float2*)&qb[r1l * H_ + s * 16 + 2 * t + 8];
        split2(v0.x * s0, v0.y * s0, qh[s][0], ql[s][0]);
        split2(v1.x * s1, v1.y * s1, qh[s][1], ql[s][1]);
        split2(v2.x * s0, v2.y * s0, qh[s][2], ql[s][2]);
        split2(v3.x * s1, v3.y * s1, qh[s][3], ql[s][3]);
    }

    float l0 = 0.f, l1 = 0.f;   // per-thread partial; reduced after the loop
    float o[4][4] = {};

    // loop-invariant fragment offsets
    const int koff = g * 20 + t * 4;           // K fragment base
    const int voff = g * 36 + t * 8;           // V fragment base

    fill_tile(sbase, 0, bh, 0, maskb);

    for (int kt = 0; kt < 32; kt++) {
        const int buf = (kt & 1) ? BUFSZ : 0;
        cp_wait0();
        __syncthreads();
        if (kt + 1 < 32)
            fill_tile(sbase, (kt & 1) ? 0 : BUFSZ, bh, kt + 1, maskb);

        const uint32_t* KH = smu + buf + OKH;
        const uint32_t* KL = smu + buf + OKL;
        const uint32_t* VH = smu + buf + OVH;
        const uint32_t* VL = smu + buf + OVL;
        const int*      MS = (const int*)(smu + buf + OMS);

        // ---- per-half pipeline: S -> exp2/pack -> PV ----
        #pragma unroll
        for (int half = 0; half < 2; half++) {
            // S (bf16x3) for 4 key-col groups
            float c[4][4] = {};
            #pragma unroll
            for (int jj = 0; jj < 4; jj++) {
                int j = half * 4 + jj;
                uint4 bhw = *(const uint4*)(KH + j * 160 + koff);
                uint4 blw = *(const uint4*)(KL + j * 160 + koff);
                mma16(c[jj], qh[0], bhw.x, bhw.y);
                mma16(c[jj], qh[1], bhw.z, bhw.w);
                mma16(c[jj], ql[0], bhw.x, bhw.y);
                mma16(c[jj], ql[1], bhw.z, bhw.w);
                mma16(c[jj], qh[0], blw.x, blw.y);
                mma16(c[jj], qh[1], blw.z, blw.w);
            }
            if (!noMask) {
                #pragma unroll
                for (int jj = 0; jj < 4; jj++) {
                    int j = half * 4 + jj;
                    int2 mv = *(const int2*)(MS + j * 8 + 2 * t);
                    if (mv.x == 0) { c[jj][0] = -1e9f; c[jj][2] = -1e9f; }
                    if (mv.y == 0) { c[jj][1] = -1e9f; c[jj][3] = -1e9f; }
                }
            }
            // exp2 + pack into PV A-fragments (2 k16-chunks this half)
            uint32_t APH[2][4], APL[2][4];
            #pragma unroll
            for (int kb2 = 0; kb2 < 2; kb2++) {
                float pA0 = ex2f(c[2*kb2][0]   - EOFF2);
                float pA1 = ex2f(c[2*kb2][1]   - EOFF2);
                float pA2 = ex2f(c[2*kb2][2]   - EOFF2);
                float pA3 = ex2f(c[2*kb2][3]   - EOFF2);
                float pB0 = ex2f(c[2*kb2+1][0] - EOFF2);
                float pB1 = ex2f(c[2*kb2+1][1] - EOFF2);
                float pB2 = ex2f(c[2*kb2+1][2] - EOFF2);
                float pB3 = ex2f(c[2*kb2+1][3] - EOFF2);
                l0 += pA0 + pA1 + pB0 + pB1;
                l1 += pA2 + pA3 + pB2 + pB3;
                split2(pA0, pA1, APH[kb2][0], APL[kb2][0]);
                split2(pA2, pA3, APH[kb2][1], APL[kb2][1]);
                split2(pB0, pB1, APH[kb2][2], APL[kb2][2]);
                split2(pB2, pB3, APH[kb2][3], APL[kb2][3]);
            }
            // PV (bf16x3) for this half's 2 k16-chunks
            #pragma unroll
            for (int nb = 0; nb < 4; nb++) {
                uint4 vh = *(const uint4*)(VH + nb * 288 + voff + half * 4);
                uint4 vl = *(const uint4*)(VL + nb * 288 + voff + half * 4);
                mma16(o[nb], APH[0], vh.x, vh.y);
                mma16(o[nb], APH[1], vh.z, vh.w);
                mma16(o[nb], APL[0], vh.x, vh.y);
                mma16(o[nb], APL[1], vh.z, vh.w);
                mma16(o[nb], APH[0], vl.x, vl.y);
                mma16(o[nb], APH[1], vl.z, vl.w);
            }
        }
    }

    // ---- one-time l reduction across the 4-lane groups ----
    l0 += __shfl_xor_sync(0xffffffffu, l0, 1);
    l0 += __shfl_xor_sync(0xffffffffu, l0, 2);
    l1 += __shfl_xor_sync(0xffffffffu, l1, 1);
    l1 += __shfl_xor_sync(0xffffffffu, l1, 2);

    // ---- normalize + store (fused head transpose) ----
    float inv0 = 1.f / l0, inv1 = 1.f / l1;
    #pragma unroll
    for (int nb = 0; nb < 4; nb++) {
        int col = h * DH_ + nb * 8 + 2 * t;
        float2 w0 = make_float2(o[nb][0] * inv0, o[nb][1] * inv0);
        float2 w1 = make_float2(o[nb][2] * inv1, o[nb][3] * inv1);
        *(float2*)&g_hidden[(size_t)(b * L_ + q0 + r0l) * H_ + col] = w0;
        *(float2*)&g_hidden[(size_t)(b * L_ + q0 + r1l) * H_ + col] = w1;
    }
}

// ---------------------------------------------------------------------------
// Launch. Inputs: 0=q 1=k 2=v 3=k_b 4=mask 5=scale_w 6=Wb 7=bb 8=Ww 9=bw
// ---------------------------------------------------------------------------
extern "C" void kernel_launch(void* const* d_in, const int* in_sizes, int n_in,
                              void* d_out, int out_size)
{
    const float* q       = (const float*)d_in[0];
    const float* k       = (const float*)d_in[1];
    const float* v       = (const float*)d_in[2];
    const float* k_b     = (const float*)d_in[3];
    const int*   mask    = (const int*)  d_in[4];
    const float* scale_w = (const float*)d_in[5];
    const float* Wb      = (const float*)d_in[6];
    const float* bb      = (const float*)d_in[7];
    const float* Ww      = (const float*)d_in[8];
    const float* bw      = (const float*)d_in[9];
    float* out = (float*)d_out;

    cudaFuncSetAttribute(attn_tc, cudaFuncAttributeMaxDynamicSharedMemorySize,
                         ATTN_SMEM_BYTES);
    cudaFuncSetAttribute(gemm_tc<true>,
                         cudaFuncAttributeMaxDynamicSharedMemorySize, GEMM_SMEM_BYTES);
    cudaFuncSetAttribute(gemm_tc<false>,
                         cudaFuncAttributeMaxDynamicSharedMemorySize, GEMM_SMEM_BYTES);

    // mask all-ones flags + V split/transpose prep
    maskflag<<<B_, 128>>>(mask);
    vprep<<<B_ * NH_ * 32, 128>>>(v);

    // keff = k_b @ Wb^T + bb + k   (written directly as split bf16 words)
    gemm_tc<true><<<dim3(H_ / 64, M_ / 128), 256, GEMM_SMEM_BYTES>>>(
        k_b, Wb, bb, k, nullptr);

    // hidden = attention(q, keff, v)
    attn_tc<<<dim3(L_ / 128, NH_, B_), 256, ATTN_SMEM_BYTES>>>(q, mask, scale_w);

    // out = hidden @ Ww^T + bw
    gemm_tc<false><<<dim3(H_ / 64, M_ / 128), 256, GEMM_SMEM_BYTES>>>(
        nullptr, Ww, bw, nullptr, out);
}